// round 7
// baseline (speedup 1.0000x reference)
#include <cuda_runtime.h>
#include <cuda_bf16.h>
#include <cstdint>

// E8 lattice quantizer — bulk-DMA streaming pipeline.
// Persistent CTAs; each tile: cp.async.bulk (global->smem, mbarrier complete_tx),
// compute from SMEM, cp.async.bulk (smem->global, bulk_group). Double-buffered
// in and out. Math identical to the rel_err=0.0 kernels.

#define TILE_ROWS   256
#define TILE_BYTES  (TILE_ROWS * 32)   // 8 KB
#define NTHREADS    256

struct Coset {
    float s;
    float add;
    int   oh;
};

__device__ __forceinline__ Coset d8_pass(const float x[8], float off, float fout[8]) {
    float dk, sumf, sumd2;
    int oh = 1;
    {
        float xi = x[0] - off;
        float fi = rintf(xi);          // round-half-to-even == jnp.round
        float di = xi - fi;
        fout[0] = fi + off;
        sumf  = fi;
        sumd2 = di * di;
        dk    = di;
    }
#pragma unroll
    for (int i = 1; i < 8; i++) {
        float xi = x[i] - off;
        float fi = rintf(xi);
        float di = xi - fi;
        fout[i] = fi + off;
        sumf += fi;
        sumd2 = fmaf(di, di, sumd2);
        if (fabsf(di) > fabsf(dk)) { dk = di; oh = 1 << i; }  // strict >: first max
    }
    float fix = (dk < 0.0f) ? -1.0f : 1.0f;
    int sg = (int)sumf + (int)fix;
    bool ge = ((sg & 1) == 0);
    float m = fabsf(dk);
    Coset c;
    c.s   = ge ? fmaf(-2.0f, m, sumd2 + 1.0f) : sumd2;
    c.add = ge ? fix : 0.0f;
    c.oh  = oh;
    return c;
}

__device__ __forceinline__ void e8_row(const float x[8], float y[8]) {
    float y1[8], y2[8];
    Coset c1 = d8_pass(x, 0.0f, y1);
    Coset c2 = d8_pass(x, 0.5f, y2);
    bool use2 = (c2.s < c1.s);        // strict: ties -> coset 1
    float add = use2 ? c2.add : c1.add;
    int   oh  = use2 ? c2.oh  : c1.oh;
#pragma unroll
    for (int i = 0; i < 8; i++) {
        float fi = use2 ? y2[i] : y1[i];
        if (oh & (1 << i)) fi += add;
        y[i] = fi;
    }
}

__device__ __forceinline__ uint32_t smem_u32(const void* p) {
    return (uint32_t)__cvta_generic_to_shared(p);
}

__device__ __forceinline__ void mbar_init(uint32_t mbar, uint32_t count) {
    asm volatile("mbarrier.init.shared.b64 [%0], %1;" :: "r"(mbar), "r"(count) : "memory");
}
__device__ __forceinline__ void mbar_expect_tx(uint32_t mbar, uint32_t bytes) {
    asm volatile("mbarrier.arrive.expect_tx.shared.b64 _, [%0], %1;"
                 :: "r"(mbar), "r"(bytes) : "memory");
}
__device__ __forceinline__ void mbar_wait(uint32_t mbar, uint32_t parity) {
    asm volatile(
        "{\n\t"
        ".reg .pred P;\n\t"
        "WAIT_%=:\n\t"
        "mbarrier.try_wait.parity.acquire.cta.shared::cta.b64 P, [%0], %1, 0x989680;\n\t"
        "@P bra.uni DONE_%=;\n\t"
        "bra.uni WAIT_%=;\n\t"
        "DONE_%=:\n\t"
        "}"
        :: "r"(mbar), "r"(parity) : "memory");
}
__device__ __forceinline__ void bulk_g2s(uint32_t dst_smem, const void* src, uint32_t bytes,
                                         uint32_t mbar) {
    asm volatile("cp.async.bulk.shared::cta.global.mbarrier::complete_tx::bytes "
                 "[%0], [%1], %2, [%3];"
                 :: "r"(dst_smem), "l"(src), "r"(bytes), "r"(mbar) : "memory");
}
__device__ __forceinline__ void bulk_s2g(void* dst, uint32_t src_smem, uint32_t bytes) {
    asm volatile("cp.async.bulk.global.shared::cta.bulk_group [%0], [%1], %2;"
                 :: "l"(dst), "r"(src_smem), "r"(bytes) : "memory");
}

__global__ void __launch_bounds__(NTHREADS) e8_quantize_pipe(
    const float* __restrict__ in, float* __restrict__ out, int num_tiles) {
    __shared__ alignas(128) float s_in[2][TILE_ROWS * 8];
    __shared__ alignas(128) float s_out[2][TILE_ROWS * 8];
    __shared__ alignas(8) uint64_t s_mbar[2];

    int tid = threadIdx.x;
    uint32_t mb0 = smem_u32(&s_mbar[0]);
    uint32_t mb1 = smem_u32(&s_mbar[1]);

    if (tid == 0) {
        mbar_init(mb0, 1);
        mbar_init(mb1, 1);
        asm volatile("fence.proxy.async.shared::cta;" ::: "memory");
    }
    __syncthreads();

    // Prologue: issue loads for this CTA's first two tiles.
    long t0 = blockIdx.x;
    long t1 = blockIdx.x + (long)gridDim.x;
    if (tid == 0) {
        if (t0 < num_tiles) {
            mbar_expect_tx(mb0, TILE_BYTES);
            bulk_g2s(smem_u32(s_in[0]), in + t0 * (TILE_ROWS * 8L), TILE_BYTES, mb0);
        }
        if (t1 < num_tiles) {
            mbar_expect_tx(mb1, TILE_BYTES);
            bulk_g2s(smem_u32(s_in[1]), in + t1 * (TILE_ROWS * 8L), TILE_BYTES, mb1);
        }
    }

    int ph[2] = {0, 0};
    int seq = 0;
    for (long tile = blockIdx.x; tile < num_tiles; tile += gridDim.x, seq++) {
        int s = seq & 1;
        uint32_t mb = s ? mb1 : mb0;

        // Wait for this stage's input tile.
        mbar_wait(mb, ph[s]);
        ph[s] ^= 1;

        // Ensure out-buffer s is no longer being read by the store from seq-2.
        if (tid == 0) {
            asm volatile("cp.async.bulk.wait_group.read 1;" ::: "memory");
        }
        __syncthreads();

        // Compute: 1 row per thread.
        {
            const float* ip = &s_in[s][tid * 8];
            float x[8];
            float4 v0 = *(const float4*)(ip);
            float4 v1 = *(const float4*)(ip + 4);
            x[0]=v0.x; x[1]=v0.y; x[2]=v0.z; x[3]=v0.w;
            x[4]=v1.x; x[5]=v1.y; x[6]=v1.z; x[7]=v1.w;
            float y[8];
            e8_row(x, y);
            float* op = &s_out[s][tid * 8];
            *(float4*)(op)     = make_float4(y[0], y[1], y[2], y[3]);
            *(float4*)(op + 4) = make_float4(y[4], y[5], y[6], y[7]);
        }
        __syncthreads();   // all reads of s_in[s] and writes of s_out[s] done

        if (tid == 0) {
            // Refill this input buffer with tile seq+2 (if any).
            long next = tile + 2L * gridDim.x;
            if (next < num_tiles) {
                mbar_expect_tx(mb, TILE_BYTES);
                bulk_g2s(smem_u32(s_in[s]), in + next * (TILE_ROWS * 8L), TILE_BYTES, mb);
            }
            // Make generic STS visible to the async proxy, then bulk-store out.
            asm volatile("fence.proxy.async.shared::cta;" ::: "memory");
            bulk_s2g(out + tile * (TILE_ROWS * 8L), smem_u32(s_out[s]), TILE_BYTES);
            asm volatile("cp.async.bulk.commit_group;" ::: "memory");
        }
    }

    // Drain outstanding bulk stores (defensive; grid completion also waits).
    if (tid == 0) {
        asm volatile("cp.async.bulk.wait_group.read 0;" ::: "memory");
    }
}

// Tail: plain per-row kernel for rows not covered by full tiles (unused for N=8388608).
__global__ void e8_quantize_tail(const float* __restrict__ in, float* __restrict__ out,
                                 int first_row, int n_rows) {
    int r = first_row + blockIdx.x * blockDim.x + threadIdx.x;
    if (r >= n_rows) return;
    float x[8];
#pragma unroll
    for (int i = 0; i < 8; i++) x[i] = in[8L * r + i];
    float y[8];
    e8_row(x, y);
#pragma unroll
    for (int i = 0; i < 8; i++) out[8L * r + i] = y[i];
}

extern "C" void kernel_launch(void* const* d_in, const int* in_sizes, int n_in,
                              void* d_out, int out_size) {
    const float* in = (const float*)d_in[0];
    float* out = (float*)d_out;
    int n_rows = in_sizes[0] / 8;
    int num_tiles = n_rows / TILE_ROWS;

    int grid = 148 * 4;               // persistent: ~4 CTAs/SM (32KB smem each fits)
    if (grid > num_tiles) grid = num_tiles > 0 ? num_tiles : 1;
    if (num_tiles > 0) {
        e8_quantize_pipe<<<grid, NTHREADS>>>(in, out, num_tiles);
    }
    int done = num_tiles * TILE_ROWS;
    if (done < n_rows) {
        int rem = n_rows - done;
        e8_quantize_tail<<<(rem + 255) / 256, 256>>>(in, out, done, n_rows);
    }
}

// round 8
// speedup vs baseline: 1.0177x; 1.0177x over previous
#include <cuda_runtime.h>
#include <cuda_bf16.h>

// E8 lattice quantizer — persistent grid-stride version of the best kernel.
// 1 row/thread/iter, 256-bit streaming ld/st with evict-first policy.
// Grid sized to exactly fill the chip (148 SMs x 8 CTAs x 256 thr), removing
// wave raggedness; memory pattern per instruction identical to the 82us kernel.

struct Coset {
    float s;    // distance^2 of chosen point
    float add;  // g_even ? fix : 0
    int   oh;   // one-hot mask of argmax coordinate
};

__device__ __forceinline__ Coset d8_pass(const float x[8], float off, float fout[8]) {
    float dk, sumf, sumd2;
    int oh = 1;
    {
        float xi = x[0] - off;
        float fi = rintf(xi);          // round-half-to-even == jnp.round
        float di = xi - fi;
        fout[0] = fi + off;
        sumf  = fi;
        sumd2 = di * di;
        dk    = di;
    }
#pragma unroll
    for (int i = 1; i < 8; i++) {
        float xi = x[i] - off;
        float fi = rintf(xi);
        float di = xi - fi;
        fout[i] = fi + off;
        sumf += fi;
        sumd2 = fmaf(di, di, sumd2);
        if (fabsf(di) > fabsf(dk)) { dk = di; oh = 1 << i; }  // strict >: first max
    }
    float fix = (dk < 0.0f) ? -1.0f : 1.0f;   // d_k == 0 -> +1
    int sg = (int)sumf + (int)fix;            // exact small integers
    bool ge = ((sg & 1) == 0);
    float m = fabsf(dk);
    Coset c;
    c.s   = ge ? fmaf(-2.0f, m, sumd2 + 1.0f) : sumd2;
    c.add = ge ? fix : 0.0f;
    c.oh  = oh;
    return c;
}

__device__ __forceinline__ void ldg256_cs(const float* p, float x[8]) {
    asm volatile("ld.global.cs.v8.f32 {%0,%1,%2,%3,%4,%5,%6,%7}, [%8];"
                 : "=f"(x[0]), "=f"(x[1]), "=f"(x[2]), "=f"(x[3]),
                   "=f"(x[4]), "=f"(x[5]), "=f"(x[6]), "=f"(x[7])
                 : "l"(p));
}

__device__ __forceinline__ void stg256_cs(float* p, const float y[8]) {
    asm volatile("st.global.cs.v8.f32 [%0], {%1,%2,%3,%4,%5,%6,%7,%8};"
                 :: "l"(p),
                    "f"(y[0]), "f"(y[1]), "f"(y[2]), "f"(y[3]),
                    "f"(y[4]), "f"(y[5]), "f"(y[6]), "f"(y[7])
                 : "memory");
}

__global__ void __launch_bounds__(256) e8_quantize_kernel(
    const float* __restrict__ in, float* __restrict__ out, int n_rows) {
    long stride = (long)gridDim.x * blockDim.x;
    for (long t = (long)blockIdx.x * blockDim.x + threadIdx.x; t < n_rows; t += stride) {
        float x[8];
        ldg256_cs(in + 8L * t, x);

        float y1[8], y2[8];
        Coset c1 = d8_pass(x, 0.0f, y1);
        Coset c2 = d8_pass(x, 0.5f, y2);

        bool use2 = (c2.s < c1.s);   // strict: ties -> coset 1
        float add = use2 ? c2.add : c1.add;
        int   oh  = use2 ? c2.oh  : c1.oh;

        float y[8];
#pragma unroll
        for (int i = 0; i < 8; i++) {
            float fi = use2 ? y2[i] : y1[i];
            if (oh & (1 << i)) fi += add;
            y[i] = fi;
        }

        stg256_cs(out + 8L * t, y);
    }
}

extern "C" void kernel_launch(void* const* d_in, const int* in_sizes, int n_in,
                              void* d_out, int out_size) {
    const float* in = (const float*)d_in[0];
    float* out = (float*)d_out;
    int n_rows = in_sizes[0] / 8;
    int threads = 256;
    int blocks = 148 * 8;              // exactly fill the chip (occ cap at 32 regs)
    long need = ((long)n_rows + threads - 1) / threads;
    if ((long)blocks > need) blocks = (int)need;   // small-N safety
    e8_quantize_kernel<<<blocks, threads>>>(in, out, n_rows);
}

// round 9
// speedup vs baseline: 1.1473x; 1.1274x over previous
#include <cuda_runtime.h>
#include <cuda_bf16.h>

// E8 lattice quantizer — FINAL. 1 row/thread, flat launch, 256-bit streaming
// ld/st with evict-first policy, block=512. This configuration measured
// 81.98us / DRAM 80.5% / 6.38 TB/s — the mixed read+write HBM3e ceiling on
// GB300 (all compute pipes <=36%; LDG.128, LDG.256 and bulk-DMA engines all
// converge at the same bandwidth). Structural variants (2 rows/thread, split
// streams, DMA pipeline, persistent grid-stride) all regressed.

struct Coset {
    float s;    // distance^2 of chosen point
    float add;  // g_even ? fix : 0
    int   oh;   // one-hot mask of argmax coordinate
};

__device__ __forceinline__ Coset d8_pass(const float x[8], float off, float fout[8]) {
    float dk, sumf, sumd2;
    int oh = 1;
    {
        float xi = x[0] - off;
        float fi = rintf(xi);          // round-half-to-even == jnp.round
        float di = xi - fi;
        fout[0] = fi + off;
        sumf  = fi;
        sumd2 = di * di;
        dk    = di;
    }
#pragma unroll
    for (int i = 1; i < 8; i++) {
        float xi = x[i] - off;
        float fi = rintf(xi);
        float di = xi - fi;
        fout[i] = fi + off;
        sumf += fi;
        sumd2 = fmaf(di, di, sumd2);
        if (fabsf(di) > fabsf(dk)) { dk = di; oh = 1 << i; }  // strict >: first max
    }
    float fix = (dk < 0.0f) ? -1.0f : 1.0f;   // d_k == 0 -> +1
    int sg = (int)sumf + (int)fix;            // exact small integers
    bool ge = ((sg & 1) == 0);
    float m = fabsf(dk);
    Coset c;
    c.s   = ge ? fmaf(-2.0f, m, sumd2 + 1.0f) : sumd2;
    c.add = ge ? fix : 0.0f;
    c.oh  = oh;
    return c;
}

__device__ __forceinline__ void ldg256_cs(const float* p, float x[8]) {
    asm volatile("ld.global.cs.v8.f32 {%0,%1,%2,%3,%4,%5,%6,%7}, [%8];"
                 : "=f"(x[0]), "=f"(x[1]), "=f"(x[2]), "=f"(x[3]),
                   "=f"(x[4]), "=f"(x[5]), "=f"(x[6]), "=f"(x[7])
                 : "l"(p));
}

__device__ __forceinline__ void stg256_cs(float* p, const float y[8]) {
    asm volatile("st.global.cs.v8.f32 [%0], {%1,%2,%3,%4,%5,%6,%7,%8};"
                 :: "l"(p),
                    "f"(y[0]), "f"(y[1]), "f"(y[2]), "f"(y[3]),
                    "f"(y[4]), "f"(y[5]), "f"(y[6]), "f"(y[7])
                 : "memory");
}

__global__ void __launch_bounds__(512) e8_quantize_kernel(
    const float* __restrict__ in, float* __restrict__ out, int n_rows) {
    int t = blockIdx.x * blockDim.x + threadIdx.x;
    if (t >= n_rows) return;

    float x[8];
    ldg256_cs(in + 8L * t, x);

    float y1[8], y2[8];
    Coset c1 = d8_pass(x, 0.0f, y1);
    Coset c2 = d8_pass(x, 0.5f, y2);

    bool use2 = (c2.s < c1.s);   // strict: ties -> coset 1
    float add = use2 ? c2.add : c1.add;
    int   oh  = use2 ? c2.oh  : c1.oh;

    float y[8];
#pragma unroll
    for (int i = 0; i < 8; i++) {
        float fi = use2 ? y2[i] : y1[i];
        if (oh & (1 << i)) fi += add;
        y[i] = fi;
    }

    stg256_cs(out + 8L * t, y);
}

extern "C" void kernel_launch(void* const* d_in, const int* in_sizes, int n_in,
                              void* d_out, int out_size) {
    const float* in = (const float*)d_in[0];
    float* out = (float*)d_out;
    int n_rows = in_sizes[0] / 8;
    int threads = 512;
    int blocks = (n_rows + threads - 1) / threads;
    e8_quantize_kernel<<<blocks, threads>>>(in, out, n_rows);
}